// round 13
// baseline (speedup 1.0000x reference)
#include <cuda_runtime.h>
#include <cuda_bf16.h>
#include <cstdint>
#include <cstddef>

#define IN_F 4096
#define OUT_F 11008
#define TOK 32
#define NELEM (OUT_F * IN_F)     /* 45,088,768 */
#define N4 (NELEM / 4)           /* 11,272,192 */
#define RBLOCKS 1184

#define MTILES 86                /* OUT_F / 128 */
#define SPLITS 32
#define KSP (IN_F / SPLITS)      /* 128 k per item */
#define PK (KSP + 8)             /* 136: padded row for ldmatrix */
#define XSMEM (2 * TOK * PK * 2) /* hi+lo bf16: 17,408 B */

/* per-warp W ring: 3 buffers x 16 rows x 144B */
#define WROW 144
#define WBUF (16 * WROW)         /* 2304 B */
#define WNBUF 3
#define WRING (WNBUF * WBUF)     /* 6912 B per warp */
#define GEMM_SMEM (XSMEM + 8 * WRING)   /* 72,704 B -> 3 CTAs/SM */

#define NSTAGE (KSP / 32)        /* 4 stages of k32 */

/* ------------------------------------------------------------------ */
__device__ float                        g_partials[RBLOCKS];
__device__ float                        g_scale;
__device__ unsigned                     g_thr_bits;
__device__ __align__(16) __nv_bfloat16  g_xhi[TOK * IN_F];
__device__ __align__(16) __nv_bfloat16  g_xlo[TOK * IN_F];
__device__ float                        g_part[SPLITS][TOK * OUT_F];

/* ------------------------------------------------------------------ */
__device__ __forceinline__ uint32_t smem_u32(const void* p) {
    uint32_t a;
    asm("{ .reg .u64 t; cvta.to.shared.u64 t, %1; cvt.u32.u64 %0, t; }"
        : "=r"(a) : "l"(p));
    return a;
}

/* ternarize one fp32 (bit pattern) -> bf16 half in {0xBF80, 0x0000, 0x3F80} */
__device__ __forceinline__ uint32_t tern(uint32_t u, uint32_t thr) {
    uint32_t h = 0x3F80u | ((u >> 16) & 0x8000u);
    return ((u & 0x7FFFFFFFu) > thr) ? h : 0u;
}

__device__ __forceinline__ uint32_t tpack(float a, float b, uint32_t thr) {
    return __byte_perm(tern(__float_as_uint(a), thr),
                       tern(__float_as_uint(b), thr), 0x5410);
}

__device__ __forceinline__ void ldsm_x4(uint32_t* r, uint32_t addr) {
    asm volatile("ldmatrix.sync.aligned.m8n8.x4.shared.b16 {%0,%1,%2,%3}, [%4];"
                 : "=r"(r[0]), "=r"(r[1]), "=r"(r[2]), "=r"(r[3]) : "r"(addr));
}

__device__ __forceinline__ void mma_bf16(float* d, const uint32_t* a,
                                         uint32_t b0, uint32_t b1) {
    asm volatile(
        "mma.sync.aligned.m16n8k16.row.col.f32.bf16.bf16.f32 "
        "{%0,%1,%2,%3}, {%4,%5,%6,%7}, {%8,%9}, {%0,%1,%2,%3};"
        : "+f"(d[0]), "+f"(d[1]), "+f"(d[2]), "+f"(d[3])
        : "r"(a[0]), "r"(a[1]), "r"(a[2]), "r"(a[3]), "r"(b0), "r"(b1));
}

__device__ __forceinline__ void cp16(uint32_t dst, const void* src) {
    asm volatile("cp.async.cg.shared.global [%0], [%1], 16;"
                 :: "r"(dst), "l"(src) : "memory");
}

__device__ __forceinline__ float2 lds_v2(uint32_t addr) {
    float2 v;
    asm volatile("ld.shared.v2.f32 {%0,%1}, [%2];"
                 : "=f"(v.x), "=f"(v.y) : "r"(addr));
    return v;
}

/* ------------------------------------------------------------------ */
/* pass 1: abs-sum partials over W                                     */
/* ------------------------------------------------------------------ */
__global__ void k_reduce(const float* __restrict__ w) {
    __shared__ float sm[256];
    const float4* w4 = reinterpret_cast<const float4*>(w);
    int idx = blockIdx.x * 256 + threadIdx.x;
    int stride = gridDim.x * 256;
    float s0 = 0.f, s1 = 0.f, s2 = 0.f, s3 = 0.f;
    int i = idx;
    for (; i + 3 * stride < N4; i += 4 * stride) {
        float4 a = w4[i];
        float4 b = w4[i + stride];
        float4 c = w4[i + 2 * stride];
        float4 d = w4[i + 3 * stride];
        s0 += fabsf(a.x) + fabsf(a.y) + fabsf(a.z) + fabsf(a.w);
        s1 += fabsf(b.x) + fabsf(b.y) + fabsf(b.z) + fabsf(b.w);
        s2 += fabsf(c.x) + fabsf(c.y) + fabsf(c.z) + fabsf(c.w);
        s3 += fabsf(d.x) + fabsf(d.y) + fabsf(d.z) + fabsf(d.w);
    }
    for (; i < N4; i += stride) {
        float4 a = w4[i];
        s0 += fabsf(a.x) + fabsf(a.y) + fabsf(a.z) + fabsf(a.w);
    }
    sm[threadIdx.x] = (s0 + s1) + (s2 + s3);
    __syncthreads();
    for (int o = 128; o > 0; o >>= 1) {
        if (threadIdx.x < o) sm[threadIdx.x] += sm[threadIdx.x + o];
        __syncthreads();
    }
    if (threadIdx.x == 0) g_partials[blockIdx.x] = sm[0];
}

/* ------------------------------------------------------------------ */
__global__ void k_finalize() {
    __shared__ double sd[256];
    double s = 0.0;
    for (int i = threadIdx.x; i < RBLOCKS; i += 256) s += (double)g_partials[i];
    sd[threadIdx.x] = s;
    __syncthreads();
    for (int o = 128; o > 0; o >>= 1) {
        if (threadIdx.x < o) sd[threadIdx.x] += sd[threadIdx.x + o];
        __syncthreads();
    }
    if (threadIdx.x == 0) {
        double mean = sd[0] / (double)NELEM;
        float am = fmaxf((float)mean, 1e-5f);
        g_scale = am;
        g_thr_bits = __float_as_uint(0.7f * am);
    }
}

/* ------------------------------------------------------------------ */
__global__ void k_xsplit(const float* __restrict__ x) {
    int i = blockIdx.x * blockDim.x + threadIdx.x;
    if (i < TOK * IN_F) {
        float v = x[i];
        __nv_bfloat16 h = __float2bfloat16(v);
        g_xhi[i] = h;
        g_xlo[i] = __float2bfloat16(v - __bfloat162float(h));
    }
}

/* ------------------------------------------------------------------ */
/* pass 4: partial dequant-GEMM. grid = 86*32 = 2752 CTAs x 256 thr,   */
/* 3 CTAs/SM. Item = (M-tile 128 outs, K-chunk 128). 8 warps x 16 outs.*/
/* W: per-warp cp.async ring, 3 bufs x k32, 4 stages, wait_group 2.    */
/* One commit per stage (empty in tail) keeps the group count exact.   */
/* ------------------------------------------------------------------ */
__global__ __launch_bounds__(256, 3) void k_gemm(const float* __restrict__ w) {
    extern __shared__ __align__(16) char smem[];
    uint32_t sbase = smem_u32(smem);
    const uint32_t lo_off = TOK * PK * 2;

    const int tid = threadIdx.x;
    const int lane = tid & 31;
    const int wid = tid >> 5;

    const int tile = (MTILES - 1) - (blockIdx.x >> 5);   /* reverse order */
    const int ks = blockIdx.x & 31;
    const int k0 = ks * KSP;

    const int o_base = tile * 128 + wid * 16;

    /* ---- per-warp W ring setup ---- */
    const uint32_t wring = sbase + XSMEM + wid * WRING;
    const int lrow = lane >> 3;                 /* 0..3: row within op  */
    const int lcol = lane & 7;                  /* 16B column           */
    const float* gw = w + (size_t)o_base * IN_F + k0;
    const float* gsrc = gw + (size_t)lrow * IN_F + lcol * 4;
    const uint32_t sdst = wring + lrow * WROW + lcol * 16;

    /* issue stage s into buffer b (k columns s*32..s*32+31) */
#define W_ISSUE(s, b)                                                        \
    do {                                                                     \
        _Pragma("unroll")                                                    \
        for (int op = 0; op < 4; op++)                                       \
            cp16(sdst + (b) * WBUF + op * 4 * WROW,                          \
                 gsrc + (size_t)op * 4 * IN_F + (s) * 32);                   \
        asm volatile("cp.async.commit_group;" ::: "memory");                 \
    } while (0)

    /* prologue: fill all 3 buffers (overlaps with x staging below) */
    W_ISSUE(0, 0); W_ISSUE(1, 1); W_ISSUE(2, 2);

    /* ---- stage x chunk (hi & lo) into padded SMEM ---- */
    {
        const uint4* srch = reinterpret_cast<const uint4*>(g_xhi);
        const uint4* srcl = reinterpret_cast<const uint4*>(g_xlo);
#pragma unroll
        for (int e = 0; e < (TOK * KSP / 8) / 256; e++) {
            int g = e * 256 + tid;
            int tok = g >> 4;                   /* KSP/8 = 16 groups/row */
            int kg = g & 15;
            uint4 hv = srch[(tok * IN_F + k0) / 8 + kg];
            uint4 lv = srcl[(tok * IN_F + k0) / 8 + kg];
            uint32_t dst = sbase + (uint32_t)(tok * PK + kg * 8) * 2;
            asm volatile("st.shared.v4.b32 [%0], {%1,%2,%3,%4};"
                         :: "r"(dst), "r"(hv.x), "r"(hv.y), "r"(hv.z), "r"(hv.w)
                         : "memory");
            asm volatile("st.shared.v4.b32 [%0], {%1,%2,%3,%4};"
                         :: "r"(dst + lo_off), "r"(lv.x), "r"(lv.y), "r"(lv.z), "r"(lv.w)
                         : "memory");
        }
    }

    const uint32_t thr = g_thr_bits;
    const int kq = 2 * (lane & 3);
    const int nrow = lane >> 2;

    /* W consumption address inside a buffer */
    const uint32_t wrd = wring + nrow * WROW;

    /* ldmatrix A addresses */
    const int mrow = ((lane >> 3) & 1) * 8 + (lane & 7);
    const int mcol = (lane >> 4) * 8;
    const uint32_t am0 = sbase + (uint32_t)((0 * 16 + mrow) * PK + mcol) * 2;
    const uint32_t am1 = sbase + (uint32_t)((1 * 16 + mrow) * PK + mcol) * 2;

    float acc[2][2][4];
#pragma unroll
    for (int t = 0; t < 2; t++)
#pragma unroll
        for (int n = 0; n < 2; n++)
#pragma unroll
            for (int r = 0; r < 4; r++) acc[t][n][r] = 0.f;

    __syncthreads();   /* x tiles visible to all warps */

    /* ---- mainloop: 4 stages of k32, per-warp async pipeline ---- */
#pragma unroll 1
    for (int s = 0; s < NSTAGE; s++) {
        asm volatile("cp.async.wait_group 2;" ::: "memory");
        __syncwarp();

        const int buf = s % WNBUF;
        const uint32_t wb = wrd + buf * WBUF;
#pragma unroll
        for (int j = 0; j < 2; j++) {
            const int kk = s * 32 + j * 16;
            const uint32_t o4 = (uint32_t)(j * 16 + kq) * 4;

            float2 u00 = lds_v2(wb + o4);
            float2 u01 = lds_v2(wb + o4 + 32);
            float2 u10 = lds_v2(wb + 8 * WROW + o4);
            float2 u11 = lds_v2(wb + 8 * WROW + o4 + 32);

            uint32_t ah0[4], ah1[4], al0[4], al1[4];
            ldsm_x4(ah0, am0 + kk * 2);
            ldsm_x4(ah1, am1 + kk * 2);
            ldsm_x4(al0, am0 + kk * 2 + lo_off);
            ldsm_x4(al1, am1 + kk * 2 + lo_off);

            uint32_t b00 = tpack(u00.x, u00.y, thr);
            uint32_t b01 = tpack(u01.x, u01.y, thr);
            uint32_t b10 = tpack(u10.x, u10.y, thr);
            uint32_t b11 = tpack(u11.x, u11.y, thr);

            mma_bf16(acc[0][0], ah0, b00, b01);
            mma_bf16(acc[1][0], ah1, b00, b01);
            mma_bf16(acc[0][1], ah0, b10, b11);
            mma_bf16(acc[1][1], ah1, b10, b11);
            mma_bf16(acc[0][0], al0, b00, b01);
            mma_bf16(acc[1][0], al1, b00, b01);
            mma_bf16(acc[0][1], al0, b10, b11);
            mma_bf16(acc[1][1], al1, b10, b11);
        }

        __syncwarp();
        if (s + WNBUF < NSTAGE) {
            W_ISSUE(s + WNBUF, buf);
        } else {
            /* tail: empty group keeps the wait_group 2 arithmetic exact */
            asm volatile("cp.async.commit_group;" ::: "memory");
        }
    }

    /* ---- epilogue: write partials (unscaled) ---- */
    float* dst = g_part[ks];
#pragma unroll
    for (int tt = 0; tt < 2; tt++) {
#pragma unroll
        for (int nt = 0; nt < 2; nt++) {
            int tok = tt * 16 + (lane >> 2);
            int o = o_base + nt * 8 + kq;
            float2 lo2, hi2;
            lo2.x = acc[tt][nt][0];
            lo2.y = acc[tt][nt][1];
            hi2.x = acc[tt][nt][2];
            hi2.y = acc[tt][nt][3];
            *reinterpret_cast<float2*>(dst + (size_t)tok * OUT_F + o) = lo2;
            *reinterpret_cast<float2*>(dst + (size_t)(tok + 8) * OUT_F + o) = hi2;
        }
    }
#undef W_ISSUE
}

/* ------------------------------------------------------------------ */
/* pass 5: combine 32 partials, apply scale                            */
/* ------------------------------------------------------------------ */
__global__ void k_combine(float* __restrict__ out) {
    const float scale = g_scale;
    int i = blockIdx.x * 256 + threadIdx.x;      /* float4 index */
    if (i < TOK * OUT_F / 4) {
        float4 s = reinterpret_cast<const float4*>(g_part[0])[i];
#pragma unroll
        for (int p = 1; p < SPLITS; p++) {
            float4 v = reinterpret_cast<const float4*>(g_part[p])[i];
            s.x += v.x; s.y += v.y; s.z += v.z; s.w += v.w;
        }
        s.x *= scale; s.y *= scale; s.z *= scale; s.w *= scale;
        reinterpret_cast<float4*>(out)[i] = s;
    }
}

/* ------------------------------------------------------------------ */
extern "C" void kernel_launch(void* const* d_in, const int* in_sizes, int n_in,
                              void* d_out, int out_size) {
    const float* x = (const float*)d_in[0];
    const float* w = (const float*)d_in[1];
    float* out = (float*)d_out;
    (void)in_sizes; (void)n_in; (void)out_size;

    cudaFuncSetAttribute(k_gemm, cudaFuncAttributeMaxDynamicSharedMemorySize,
                         GEMM_SMEM);

    k_reduce<<<RBLOCKS, 256>>>(w);
    k_finalize<<<1, 256>>>();
    k_xsplit<<<(TOK * IN_F + 255) / 256, 256>>>(x);
    k_gemm<<<MTILES * SPLITS, 256, GEMM_SMEM>>>(w);
    k_combine<<<(TOK * OUT_F / 4 + 255) / 256, 256>>>(out);
}

// round 14
// speedup vs baseline: 1.1880x; 1.1880x over previous
#include <cuda_runtime.h>
#include <cuda_fp16.h>
#include <cstdint>
#include <cstddef>

#define IN_F 4096
#define OUT_F 11008
#define TOK 32
#define NELEM (OUT_F * IN_F)     /* 45,088,768 */
#define N4 (NELEM / 4)           /* 11,272,192 */
#define RBLOCKS 1184

#define MTILES 86                /* OUT_F / 128 */
#define SPLITS 16
#define KSP (IN_F / SPLITS)      /* 256 k per item */
#define PK (KSP + 8)             /* 264: padded row for ldmatrix */
#define XSMEM (TOK * PK * 2)     /* single fp16 copy: 16,896 B */

/* per-warp W ring: 3 buffers x 16 rows x 144B */
#define WROW 144
#define WBUF (16 * WROW)         /* 2304 B */
#define WNBUF 3
#define WRING (WNBUF * WBUF)     /* 6912 B per warp */
#define GEMM_SMEM (XSMEM + 8 * WRING)   /* 72,192 B -> 3 CTAs/SM */

#define NSTAGE (KSP / 32)        /* 8 stages of k32 */

/* ------------------------------------------------------------------ */
__device__ float                 g_partials[RBLOCKS];
__device__ float                 g_scale;
__device__ unsigned              g_thr_bits;
__device__ __align__(16) __half  g_xh[TOK * IN_F];
__device__ float                 g_part[SPLITS][TOK * OUT_F];

/* ------------------------------------------------------------------ */
__device__ __forceinline__ uint32_t smem_u32(const void* p) {
    uint32_t a;
    asm("{ .reg .u64 t; cvta.to.shared.u64 t, %1; cvt.u32.u64 %0, t; }"
        : "=r"(a) : "l"(p));
    return a;
}

/* ternarize one fp32 (bit pattern) -> fp16 half in {0xBC00, 0x0000, 0x3C00} */
__device__ __forceinline__ uint32_t tern(uint32_t u, uint32_t thr) {
    uint32_t h = 0x3C00u | ((u >> 16) & 0x8000u);
    return ((u & 0x7FFFFFFFu) > thr) ? h : 0u;
}

__device__ __forceinline__ uint32_t tpack(float a, float b, uint32_t thr) {
    return __byte_perm(tern(__float_as_uint(a), thr),
                       tern(__float_as_uint(b), thr), 0x5410);
}

__device__ __forceinline__ void ldsm_x4(uint32_t* r, uint32_t addr) {
    asm volatile("ldmatrix.sync.aligned.m8n8.x4.shared.b16 {%0,%1,%2,%3}, [%4];"
                 : "=r"(r[0]), "=r"(r[1]), "=r"(r[2]), "=r"(r[3]) : "r"(addr));
}

__device__ __forceinline__ void mma_f16(float* d, const uint32_t* a,
                                        uint32_t b0, uint32_t b1) {
    asm volatile(
        "mma.sync.aligned.m16n8k16.row.col.f32.f16.f16.f32 "
        "{%0,%1,%2,%3}, {%4,%5,%6,%7}, {%8,%9}, {%0,%1,%2,%3};"
        : "+f"(d[0]), "+f"(d[1]), "+f"(d[2]), "+f"(d[3])
        : "r"(a[0]), "r"(a[1]), "r"(a[2]), "r"(a[3]), "r"(b0), "r"(b1));
}

__device__ __forceinline__ void cp16(uint32_t dst, const void* src) {
    asm volatile("cp.async.cg.shared.global [%0], [%1], 16;"
                 :: "r"(dst), "l"(src) : "memory");
}

__device__ __forceinline__ float2 lds_v2(uint32_t addr) {
    float2 v;
    asm volatile("ld.shared.v2.f32 {%0,%1}, [%2];"
                 : "=f"(v.x), "=f"(v.y) : "r"(addr));
    return v;
}

/* ------------------------------------------------------------------ */
/* pass 1: abs-sum partials over W                                     */
/* ------------------------------------------------------------------ */
__global__ void k_reduce(const float* __restrict__ w) {
    __shared__ float sm[256];
    const float4* w4 = reinterpret_cast<const float4*>(w);
    int idx = blockIdx.x * 256 + threadIdx.x;
    int stride = gridDim.x * 256;
    float s0 = 0.f, s1 = 0.f, s2 = 0.f, s3 = 0.f;
    int i = idx;
    for (; i + 3 * stride < N4; i += 4 * stride) {
        float4 a = w4[i];
        float4 b = w4[i + stride];
        float4 c = w4[i + 2 * stride];
        float4 d = w4[i + 3 * stride];
        s0 += fabsf(a.x) + fabsf(a.y) + fabsf(a.z) + fabsf(a.w);
        s1 += fabsf(b.x) + fabsf(b.y) + fabsf(b.z) + fabsf(b.w);
        s2 += fabsf(c.x) + fabsf(c.y) + fabsf(c.z) + fabsf(c.w);
        s3 += fabsf(d.x) + fabsf(d.y) + fabsf(d.z) + fabsf(d.w);
    }
    for (; i < N4; i += stride) {
        float4 a = w4[i];
        s0 += fabsf(a.x) + fabsf(a.y) + fabsf(a.z) + fabsf(a.w);
    }
    sm[threadIdx.x] = (s0 + s1) + (s2 + s3);
    __syncthreads();
    for (int o = 128; o > 0; o >>= 1) {
        if (threadIdx.x < o) sm[threadIdx.x] += sm[threadIdx.x + o];
        __syncthreads();
    }
    if (threadIdx.x == 0) g_partials[blockIdx.x] = sm[0];
}

/* ------------------------------------------------------------------ */
__global__ void k_finalize() {
    __shared__ double sd[256];
    double s = 0.0;
    for (int i = threadIdx.x; i < RBLOCKS; i += 256) s += (double)g_partials[i];
    sd[threadIdx.x] = s;
    __syncthreads();
    for (int o = 128; o > 0; o >>= 1) {
        if (threadIdx.x < o) sd[threadIdx.x] += sd[threadIdx.x + o];
        __syncthreads();
    }
    if (threadIdx.x == 0) {
        double mean = sd[0] / (double)NELEM;
        float am = fmaxf((float)mean, 1e-5f);
        g_scale = am;
        g_thr_bits = __float_as_uint(0.7f * am);
    }
}

/* ------------------------------------------------------------------ */
__global__ void k_xsplit(const float* __restrict__ x) {
    int i = blockIdx.x * blockDim.x + threadIdx.x;
    if (i < TOK * IN_F) g_xh[i] = __float2half(x[i]);
}

/* ------------------------------------------------------------------ */
/* pass 4: partial dequant-GEMM. grid = 86*16 = 1376 CTAs x 256 thr,   */
/* 3 CTAs/SM. Item = (M-tile 128 outs, K-chunk 256). 8 warps x 16 outs.*/
/* Single fp16 x stream (ternary W exact in fp16; only x rounds).      */
/* W: per-warp cp.async ring, 3 bufs x k32, 8 stages, wait_group 2;    */
/* one commit per stage (empty in tail) keeps group count exact.       */
/* ------------------------------------------------------------------ */
__global__ __launch_bounds__(256, 3) void k_gemm(const float* __restrict__ w) {
    extern __shared__ __align__(16) char smem[];
    uint32_t sbase = smem_u32(smem);

    const int tid = threadIdx.x;
    const int lane = tid & 31;
    const int wid = tid >> 5;

    const int tile = (MTILES - 1) - (blockIdx.x >> 4);   /* reverse order */
    const int ks = blockIdx.x & 15;
    const int k0 = ks * KSP;

    const int o_base = tile * 128 + wid * 16;

    /* ---- per-warp W ring setup ---- */
    const uint32_t wring = sbase + XSMEM + wid * WRING;
    const int lrow = lane >> 3;                 /* 0..3: row within op  */
    const int lcol = lane & 7;                  /* 16B column           */
    const float* gw = w + (size_t)o_base * IN_F + k0;
    const float* gsrc = gw + (size_t)lrow * IN_F + lcol * 4;
    const uint32_t sdst = wring + lrow * WROW + lcol * 16;

    /* issue stage s into buffer b (k columns s*32..s*32+31) */
#define W_ISSUE(s, b)                                                        \
    do {                                                                     \
        _Pragma("unroll")                                                    \
        for (int op = 0; op < 4; op++)                                       \
            cp16(sdst + (b) * WBUF + op * 4 * WROW,                          \
                 gsrc + (size_t)op * 4 * IN_F + (s) * 32);                   \
        asm volatile("cp.async.commit_group;" ::: "memory");                 \
    } while (0)

    /* prologue: fill all 3 buffers (overlaps with x staging below) */
    W_ISSUE(0, 0); W_ISSUE(1, 1); W_ISSUE(2, 2);

    /* ---- stage x chunk (fp16) into padded SMEM ---- */
    {
        const uint4* srcx = reinterpret_cast<const uint4*>(g_xh);
#pragma unroll
        for (int e = 0; e < (TOK * KSP / 8) / 256; e++) {
            int g = e * 256 + tid;
            int tok = g >> 5;                   /* KSP/8 = 32 groups/row */
            int kg = g & 31;
            uint4 hv = srcx[(tok * IN_F + k0) / 8 + kg];
            uint32_t dst = sbase + (uint32_t)(tok * PK + kg * 8) * 2;
            asm volatile("st.shared.v4.b32 [%0], {%1,%2,%3,%4};"
                         :: "r"(dst), "r"(hv.x), "r"(hv.y), "r"(hv.z), "r"(hv.w)
                         : "memory");
        }
    }

    const uint32_t thr = g_thr_bits;
    const int kq = 2 * (lane & 3);
    const int nrow = lane >> 2;

    /* W consumption address inside a buffer */
    const uint32_t wrd = wring + nrow * WROW;

    /* ldmatrix A addresses */
    const int mrow = ((lane >> 3) & 1) * 8 + (lane & 7);
    const int mcol = (lane >> 4) * 8;
    const uint32_t am0 = sbase + (uint32_t)((0 * 16 + mrow) * PK + mcol) * 2;
    const uint32_t am1 = sbase + (uint32_t)((1 * 16 + mrow) * PK + mcol) * 2;

    float acc[2][2][4];
#pragma unroll
    for (int t = 0; t < 2; t++)
#pragma unroll
        for (int n = 0; n < 2; n++)
#pragma unroll
            for (int r = 0; r < 4; r++) acc[t][n][r] = 0.f;

    __syncthreads();   /* x tiles visible to all warps */

    /* ---- mainloop: 8 stages of k32, per-warp async pipeline ---- */
#pragma unroll 1
    for (int s = 0; s < NSTAGE; s++) {
        asm volatile("cp.async.wait_group 2;" ::: "memory");
        __syncwarp();

        const int buf = s % WNBUF;
        const uint32_t wb = wrd + buf * WBUF;
#pragma unroll
        for (int j = 0; j < 2; j++) {
            const int kk = s * 32 + j * 16;
            const uint32_t o4 = (uint32_t)(j * 16 + kq) * 4;

            float2 u00 = lds_v2(wb + o4);
            float2 u01 = lds_v2(wb + o4 + 32);
            float2 u10 = lds_v2(wb + 8 * WROW + o4);
            float2 u11 = lds_v2(wb + 8 * WROW + o4 + 32);

            uint32_t a0[4], a1[4];
            ldsm_x4(a0, am0 + kk * 2);
            ldsm_x4(a1, am1 + kk * 2);

            uint32_t b00 = tpack(u00.x, u00.y, thr);
            uint32_t b01 = tpack(u01.x, u01.y, thr);
            uint32_t b10 = tpack(u10.x, u10.y, thr);
            uint32_t b11 = tpack(u11.x, u11.y, thr);

            mma_f16(acc[0][0], a0, b00, b01);
            mma_f16(acc[1][0], a1, b00, b01);
            mma_f16(acc[0][1], a0, b10, b11);
            mma_f16(acc[1][1], a1, b10, b11);
        }

        __syncwarp();
        if (s + WNBUF < NSTAGE) {
            W_ISSUE(s + WNBUF, buf);
        } else {
            /* tail: empty group keeps the wait_group 2 arithmetic exact */
            asm volatile("cp.async.commit_group;" ::: "memory");
        }
    }

    /* ---- epilogue: write partials (unscaled) ---- */
    float* dst = g_part[ks];
#pragma unroll
    for (int tt = 0; tt < 2; tt++) {
#pragma unroll
        for (int nt = 0; nt < 2; nt++) {
            int tok = tt * 16 + (lane >> 2);
            int o = o_base + nt * 8 + kq;
            float2 lo2, hi2;
            lo2.x = acc[tt][nt][0];
            lo2.y = acc[tt][nt][1];
            hi2.x = acc[tt][nt][2];
            hi2.y = acc[tt][nt][3];
            *reinterpret_cast<float2*>(dst + (size_t)tok * OUT_F + o) = lo2;
            *reinterpret_cast<float2*>(dst + (size_t)(tok + 8) * OUT_F + o) = hi2;
        }
    }
#undef W_ISSUE
}

/* ------------------------------------------------------------------ */
/* pass 5: combine 16 partials, apply scale                            */
/* ------------------------------------------------------------------ */
__global__ void k_combine(float* __restrict__ out) {
    const float scale = g_scale;
    int i = blockIdx.x * 256 + threadIdx.x;      /* float4 index */
    if (i < TOK * OUT_F / 4) {
        float4 s = reinterpret_cast<const float4*>(g_part[0])[i];
#pragma unroll
        for (int p = 1; p < SPLITS; p++) {
            float4 v = reinterpret_cast<const float4*>(g_part[p])[i];
            s.x += v.x; s.y += v.y; s.z += v.z; s.w += v.w;
        }
        s.x *= scale; s.y *= scale; s.z *= scale; s.w *= scale;
        reinterpret_cast<float4*>(out)[i] = s;
    }
}

/* ------------------------------------------------------------------ */
extern "C" void kernel_launch(void* const* d_in, const int* in_sizes, int n_in,
                              void* d_out, int out_size) {
    const float* x = (const float*)d_in[0];
    const float* w = (const float*)d_in[1];
    float* out = (float*)d_out;
    (void)in_sizes; (void)n_in; (void)out_size;

    cudaFuncSetAttribute(k_gemm, cudaFuncAttributeMaxDynamicSharedMemorySize,
                         GEMM_SMEM);

    k_reduce<<<RBLOCKS, 256>>>(w);
    k_finalize<<<1, 256>>>();
    k_xsplit<<<(TOK * IN_F + 255) / 256, 256>>>(x);
    k_gemm<<<MTILES * SPLITS, 256, GEMM_SMEM>>>(w);
    k_combine<<<(TOK * OUT_F / 4 + 255) / 256, 256>>>(out);
}

// round 15
// speedup vs baseline: 1.2857x; 1.0822x over previous
#include <cuda_runtime.h>
#include <cuda_fp16.h>
#include <cstdint>
#include <cstddef>

#define IN_F 4096
#define OUT_F 11008
#define TOK 32
#define NELEM (OUT_F * IN_F)     /* 45,088,768 */
#define N4 (NELEM / 4)           /* 11,272,192 */
#define RBLOCKS 1184

#define MTILES 86                /* OUT_F / 128 */
#define SPLITS 16
#define KSP (IN_F / SPLITS)      /* 256 k per item */
#define PK (KSP + 8)             /* 264: padded row for ldmatrix */
#define XSMEM (TOK * PK * 2)     /* single fp16 copy: 16,896 B */

/* per-warp W ring: 3 buffers x 16 rows x 144B */
#define WROW 144
#define WBUF (16 * WROW)         /* 2304 B */
#define WNBUF 3
#define WRING (WNBUF * WBUF)     /* 6912 B per warp */
#define GEMM_SMEM (XSMEM + 8 * WRING)   /* 72,192 B -> 3 CTAs/SM */

#define NSTAGE (KSP / 32)        /* 8 stages of k32 */

/* ------------------------------------------------------------------ */
__device__ float                 g_partials[RBLOCKS];
__device__ float                 g_scale;
__device__ float                 g_thr;
__device__ __align__(16) __half  g_xh[TOK * IN_F];
__device__ float                 g_part[SPLITS][TOK * OUT_F];

/* ------------------------------------------------------------------ */
__device__ __forceinline__ uint32_t smem_u32(const void* p) {
    uint32_t a;
    asm("{ .reg .u64 t; cvta.to.shared.u64 t, %1; cvt.u32.u64 %0, t; }"
        : "=r"(a) : "l"(p));
    return a;
}

/* ternarize in float: FSETP/FSEL live on the fma pipe, LOP3 on alu.   */
/* exact: compare is fp32; result in {-1.0f, 0.0f, +1.0f}              */
__device__ __forceinline__ float ternf(float w, float thr) {
    float s = __int_as_float(0x3F800000u | (__float_as_uint(w) & 0x80000000u));
    return (fabsf(w) > thr) ? s : 0.0f;
}

/* pack two ternary values into one fp16x2 B-fragment word (F2FP.PACK) */
__device__ __forceinline__ uint32_t tpackf(float a, float b, float thr) {
    __half2 h = __floats2half2_rn(ternf(a, thr), ternf(b, thr));
    return *reinterpret_cast<uint32_t*>(&h);
}

__device__ __forceinline__ void ldsm_x4(uint32_t* r, uint32_t addr) {
    asm volatile("ldmatrix.sync.aligned.m8n8.x4.shared.b16 {%0,%1,%2,%3}, [%4];"
                 : "=r"(r[0]), "=r"(r[1]), "=r"(r[2]), "=r"(r[3]) : "r"(addr));
}

__device__ __forceinline__ void mma_f16(float* d, const uint32_t* a,
                                        uint32_t b0, uint32_t b1) {
    asm volatile(
        "mma.sync.aligned.m16n8k16.row.col.f32.f16.f16.f32 "
        "{%0,%1,%2,%3}, {%4,%5,%6,%7}, {%8,%9}, {%0,%1,%2,%3};"
        : "+f"(d[0]), "+f"(d[1]), "+f"(d[2]), "+f"(d[3])
        : "r"(a[0]), "r"(a[1]), "r"(a[2]), "r"(a[3]), "r"(b0), "r"(b1));
}

__device__ __forceinline__ void cp16(uint32_t dst, const void* src) {
    asm volatile("cp.async.cg.shared.global [%0], [%1], 16;"
                 :: "r"(dst), "l"(src) : "memory");
}

__device__ __forceinline__ float2 lds_v2(uint32_t addr) {
    float2 v;
    asm volatile("ld.shared.v2.f32 {%0,%1}, [%2];"
                 : "=f"(v.x), "=f"(v.y) : "r"(addr));
    return v;
}

/* ------------------------------------------------------------------ */
/* pass 1: abs-sum partials over W                                     */
/* ------------------------------------------------------------------ */
__global__ void k_reduce(const float* __restrict__ w) {
    __shared__ float sm[256];
    const float4* w4 = reinterpret_cast<const float4*>(w);
    int idx = blockIdx.x * 256 + threadIdx.x;
    int stride = gridDim.x * 256;
    float s0 = 0.f, s1 = 0.f, s2 = 0.f, s3 = 0.f;
    int i = idx;
    for (; i + 3 * stride < N4; i += 4 * stride) {
        float4 a = w4[i];
        float4 b = w4[i + stride];
        float4 c = w4[i + 2 * stride];
        float4 d = w4[i + 3 * stride];
        s0 += fabsf(a.x) + fabsf(a.y) + fabsf(a.z) + fabsf(a.w);
        s1 += fabsf(b.x) + fabsf(b.y) + fabsf(b.z) + fabsf(b.w);
        s2 += fabsf(c.x) + fabsf(c.y) + fabsf(c.z) + fabsf(c.w);
        s3 += fabsf(d.x) + fabsf(d.y) + fabsf(d.z) + fabsf(d.w);
    }
    for (; i < N4; i += stride) {
        float4 a = w4[i];
        s0 += fabsf(a.x) + fabsf(a.y) + fabsf(a.z) + fabsf(a.w);
    }
    sm[threadIdx.x] = (s0 + s1) + (s2 + s3);
    __syncthreads();
    for (int o = 128; o > 0; o >>= 1) {
        if (threadIdx.x < o) sm[threadIdx.x] += sm[threadIdx.x + o];
        __syncthreads();
    }
    if (threadIdx.x == 0) g_partials[blockIdx.x] = sm[0];
}

/* ------------------------------------------------------------------ */
/* pass 2: block 0 finalizes (double) ; other blocks split x to fp16   */
/* ------------------------------------------------------------------ */
__global__ void k_fx(const float* __restrict__ x) {
    if (blockIdx.x == 0) {
        __shared__ double sd[256];
        double s = 0.0;
        for (int i = threadIdx.x; i < RBLOCKS; i += 256)
            s += (double)g_partials[i];
        sd[threadIdx.x] = s;
        __syncthreads();
        for (int o = 128; o > 0; o >>= 1) {
            if (threadIdx.x < o) sd[threadIdx.x] += sd[threadIdx.x + o];
            __syncthreads();
        }
        if (threadIdx.x == 0) {
            double mean = sd[0] / (double)NELEM;
            float am = fmaxf((float)mean, 1e-5f);
            g_scale = am;
            g_thr = 0.7f * am;
        }
    } else {
        int i = (blockIdx.x - 1) * 256 + threadIdx.x;
        if (i < TOK * IN_F) g_xh[i] = __float2half(x[i]);
    }
}

/* ------------------------------------------------------------------ */
/* pass 3: partial dequant-GEMM. grid = 86*16 = 1376 CTAs x 256 thr,   */
/* 3 CTAs/SM. Item = (M-tile 128 outs, K-chunk 256). 8 warps x 16 outs.*/
/* Single fp16 x stream; ternarize on the fma pipe (FSETP/FSEL/F2FP).  */
/* W: per-warp cp.async ring, 3 bufs x k32, 8 stages, wait_group 2;    */
/* one commit per stage (empty in tail) keeps group count exact.       */
/* ------------------------------------------------------------------ */
__global__ __launch_bounds__(256, 3) void k_gemm(const float* __restrict__ w) {
    extern __shared__ __align__(16) char smem[];
    uint32_t sbase = smem_u32(smem);

    const int tid = threadIdx.x;
    const int lane = tid & 31;
    const int wid = tid >> 5;

    const int tile = (MTILES - 1) - (blockIdx.x >> 4);   /* reverse order */
    const int ks = blockIdx.x & 15;
    const int k0 = ks * KSP;

    const int o_base = tile * 128 + wid * 16;

    /* ---- per-warp W ring setup ---- */
    const uint32_t wring = sbase + XSMEM + wid * WRING;
    const int lrow = lane >> 3;                 /* 0..3: row within op  */
    const int lcol = lane & 7;                  /* 16B column           */
    const float* gw = w + (size_t)o_base * IN_F + k0;
    const float* gsrc = gw + (size_t)lrow * IN_F + lcol * 4;
    const uint32_t sdst = wring + lrow * WROW + lcol * 16;

    /* issue stage s into buffer b (k columns s*32..s*32+31) */
#define W_ISSUE(s, b)                                                        \
    do {                                                                     \
        _Pragma("unroll")                                                    \
        for (int op = 0; op < 4; op++)                                       \
            cp16(sdst + (b) * WBUF + op * 4 * WROW,                          \
                 gsrc + (size_t)op * 4 * IN_F + (s) * 32);                   \
        asm volatile("cp.async.commit_group;" ::: "memory");                 \
    } while (0)

    /* prologue: fill all 3 buffers (overlaps with x staging below) */
    W_ISSUE(0, 0); W_ISSUE(1, 1); W_ISSUE(2, 2);

    /* ---- stage x chunk (fp16) into padded SMEM ---- */
    {
        const uint4* srcx = reinterpret_cast<const uint4*>(g_xh);
#pragma unroll
        for (int e = 0; e < (TOK * KSP / 8) / 256; e++) {
            int g = e * 256 + tid;
            int tok = g >> 5;                   /* KSP/8 = 32 groups/row */
            int kg = g & 31;
            uint4 hv = srcx[(tok * IN_F + k0) / 8 + kg];
            uint32_t dst = sbase + (uint32_t)(tok * PK + kg * 8) * 2;
            asm volatile("st.shared.v4.b32 [%0], {%1,%2,%3,%4};"
                         :: "r"(dst), "r"(hv.x), "r"(hv.y), "r"(hv.z), "r"(hv.w)
                         : "memory");
        }
    }

    const float thr = g_thr;
    const int kq = 2 * (lane & 3);
    const int nrow = lane >> 2;

    /* W consumption address inside a buffer */
    const uint32_t wrd = wring + nrow * WROW;

    /* ldmatrix A addresses */
    const int mrow = ((lane >> 3) & 1) * 8 + (lane & 7);
    const int mcol = (lane >> 4) * 8;
    const uint32_t am0 = sbase + (uint32_t)((0 * 16 + mrow) * PK + mcol) * 2;
    const uint32_t am1 = sbase + (uint32_t)((1 * 16 + mrow) * PK + mcol) * 2;

    float acc[2][2][4];
#pragma unroll
    for (int t = 0; t < 2; t++)
#pragma unroll
        for (int n = 0; n < 2; n++)
#pragma unroll
            for (int r = 0; r < 4; r++) acc[t][n][r] = 0.f;

    __syncthreads();   /* x tiles visible to all warps */

    /* ---- mainloop: 8 stages of k32, per-warp async pipeline ---- */
#pragma unroll 1
    for (int s = 0; s < NSTAGE; s++) {
        asm volatile("cp.async.wait_group 2;" ::: "memory");
        __syncwarp();

        const int buf = s % WNBUF;
        const uint32_t wb = wrd + buf * WBUF;
#pragma unroll
        for (int j = 0; j < 2; j++) {
            const int kk = s * 32 + j * 16;
            const uint32_t o4 = (uint32_t)(j * 16 + kq) * 4;

            float2 u00 = lds_v2(wb + o4);
            float2 u01 = lds_v2(wb + o4 + 32);
            float2 u10 = lds_v2(wb + 8 * WROW + o4);
            float2 u11 = lds_v2(wb + 8 * WROW + o4 + 32);

            uint32_t a0[4], a1[4];
            ldsm_x4(a0, am0 + kk * 2);
            ldsm_x4(a1, am1 + kk * 2);

            uint32_t b00 = tpackf(u00.x, u00.y, thr);
            uint32_t b01 = tpackf(u01.x, u01.y, thr);
            uint32_t b10 = tpackf(u10.x, u10.y, thr);
            uint32_t b11 = tpackf(u11.x, u11.y, thr);

            mma_f16(acc[0][0], a0, b00, b01);
            mma_f16(acc[1][0], a1, b00, b01);
            mma_f16(acc[0][1], a0, b10, b11);
            mma_f16(acc[1][1], a1, b10, b11);
        }

        __syncwarp();
        if (s + WNBUF < NSTAGE) {
            W_ISSUE(s + WNBUF, buf);
        } else {
            /* tail: empty group keeps the wait_group 2 arithmetic exact */
            asm volatile("cp.async.commit_group;" ::: "memory");
        }
    }

    /* ---- epilogue: write partials (unscaled) ---- */
    float* dst = g_part[ks];
#pragma unroll
    for (int tt = 0; tt < 2; tt++) {
#pragma unroll
        for (int nt = 0; nt < 2; nt++) {
            int tok = tt * 16 + (lane >> 2);
            int o = o_base + nt * 8 + kq;
            float2 lo2, hi2;
            lo2.x = acc[tt][nt][0];
            lo2.y = acc[tt][nt][1];
            hi2.x = acc[tt][nt][2];
            hi2.y = acc[tt][nt][3];
            *reinterpret_cast<float2*>(dst + (size_t)tok * OUT_F + o) = lo2;
            *reinterpret_cast<float2*>(dst + (size_t)(tok + 8) * OUT_F + o) = hi2;
        }
    }
#undef W_ISSUE
}

/* ------------------------------------------------------------------ */
/* pass 4: combine 16 partials, apply scale                            */
/* ------------------------------------------------------------------ */
__global__ void k_combine(float* __restrict__ out) {
    const float scale = g_scale;
    int i = blockIdx.x * 256 + threadIdx.x;      /* float4 index */
    if (i < TOK * OUT_F / 4) {
        float4 s = reinterpret_cast<const float4*>(g_part[0])[i];
#pragma unroll
        for (int p = 1; p < SPLITS; p++) {
            float4 v = reinterpret_cast<const float4*>(g_part[p])[i];
            s.x += v.x; s.y += v.y; s.z += v.z; s.w += v.w;
        }
        s.x *= scale; s.y *= scale; s.z *= scale; s.w *= scale;
        reinterpret_cast<float4*>(out)[i] = s;
    }
}

/* ------------------------------------------------------------------ */
extern "C" void kernel_launch(void* const* d_in, const int* in_sizes, int n_in,
                              void* d_out, int out_size) {
    const float* x = (const float*)d_in[0];
    const float* w = (const float*)d_in[1];
    float* out = (float*)d_out;
    (void)in_sizes; (void)n_in; (void)out_size;

    cudaFuncSetAttribute(k_gemm, cudaFuncAttributeMaxDynamicSharedMemorySize,
                         GEMM_SMEM);

    k_reduce<<<RBLOCKS, 256>>>(w);
    k_fx<<<1 + (TOK * IN_F + 255) / 256, 256>>>(x);
    k_gemm<<<MTILES * SPLITS, 256, GEMM_SMEM>>>(w);
    k_combine<<<(TOK * OUT_F / 4 + 255) / 256, 256>>>(out);
}

// round 16
// speedup vs baseline: 1.3625x; 1.0598x over previous
#include <cuda_runtime.h>
#include <cuda_fp16.h>
#include <cstdint>
#include <cstddef>

#define IN_F 4096
#define OUT_F 11008
#define TOK 32
#define NELEM (OUT_F * IN_F)     /* 45,088,768 */
#define N4 (NELEM / 4)           /* 11,272,192 */
#define RBLOCKS 1184

#define MTILES 86                /* OUT_F / 128 */
#define SPLITS 16
#define KSP (IN_F / SPLITS)      /* 256 k per item */
#define PK (KSP + 8)             /* 264: padded row for ldmatrix */
#define XSMEM (TOK * PK * 2)     /* single fp16 copy: 16,896 B */

/* per-warp W ring: 3 buffers x 16 rows x 144B */
#define WROW 144
#define WBUF (16 * WROW)         /* 2304 B */
#define WNBUF 3
#define WRING (WNBUF * WBUF)     /* 6912 B per warp */
#define GEMM_SMEM (XSMEM + 8 * WRING)   /* 72,192 B -> 3 CTAs/SM */

#define NSTAGE (KSP / 32)        /* 8 stages of k32 */

/* ------------------------------------------------------------------ */
__device__ float                 g_partials[RBLOCKS];
__device__ float                 g_scale;
__device__ float                 g_thr;
__device__ __align__(16) __half  g_xh[TOK * IN_F];
__device__ __align__(16) __half  g_part[SPLITS][TOK * OUT_F];  /* fp16 partials */

/* ------------------------------------------------------------------ */
__device__ __forceinline__ uint32_t smem_u32(const void* p) {
    uint32_t a;
    asm("{ .reg .u64 t; cvta.to.shared.u64 t, %1; cvt.u32.u64 %0, t; }"
        : "=r"(a) : "l"(p));
    return a;
}

/* ternarize in float: FSETP/FSEL live on the fma pipe, LOP3 on alu.   */
/* exact: compare is fp32; result in {-1.0f, 0.0f, +1.0f}              */
__device__ __forceinline__ float ternf(float w, float thr) {
    float s = __int_as_float(0x3F800000u | (__float_as_uint(w) & 0x80000000u));
    return (fabsf(w) > thr) ? s : 0.0f;
}

/* pack two ternary values into one fp16x2 B-fragment word (F2FP.PACK) */
__device__ __forceinline__ uint32_t tpackf(float a, float b, float thr) {
    __half2 h = __floats2half2_rn(ternf(a, thr), ternf(b, thr));
    return *reinterpret_cast<uint32_t*>(&h);
}

__device__ __forceinline__ void ldsm_x4(uint32_t* r, uint32_t addr) {
    asm volatile("ldmatrix.sync.aligned.m8n8.x4.shared.b16 {%0,%1,%2,%3}, [%4];"
                 : "=r"(r[0]), "=r"(r[1]), "=r"(r[2]), "=r"(r[3]) : "r"(addr));
}

__device__ __forceinline__ void mma_f16(float* d, const uint32_t* a,
                                        uint32_t b0, uint32_t b1) {
    asm volatile(
        "mma.sync.aligned.m16n8k16.row.col.f32.f16.f16.f32 "
        "{%0,%1,%2,%3}, {%4,%5,%6,%7}, {%8,%9}, {%0,%1,%2,%3};"
        : "+f"(d[0]), "+f"(d[1]), "+f"(d[2]), "+f"(d[3])
        : "r"(a[0]), "r"(a[1]), "r"(a[2]), "r"(a[3]), "r"(b0), "r"(b1));
}

__device__ __forceinline__ void cp16(uint32_t dst, const void* src) {
    asm volatile("cp.async.cg.shared.global [%0], [%1], 16;"
                 :: "r"(dst), "l"(src) : "memory");
}

__device__ __forceinline__ float2 lds_v2(uint32_t addr) {
    float2 v;
    asm volatile("ld.shared.v2.f32 {%0,%1}, [%2];"
                 : "=f"(v.x), "=f"(v.y) : "r"(addr));
    return v;
}

/* ------------------------------------------------------------------ */
/* pass 1: abs-sum partials over W                                     */
/* ------------------------------------------------------------------ */
__global__ void k_reduce(const float* __restrict__ w) {
    __shared__ float sm[256];
    const float4* w4 = reinterpret_cast<const float4*>(w);
    int idx = blockIdx.x * 256 + threadIdx.x;
    int stride = gridDim.x * 256;
    float s0 = 0.f, s1 = 0.f, s2 = 0.f, s3 = 0.f;
    int i = idx;
    for (; i + 3 * stride < N4; i += 4 * stride) {
        float4 a = w4[i];
        float4 b = w4[i + stride];
        float4 c = w4[i + 2 * stride];
        float4 d = w4[i + 3 * stride];
        s0 += fabsf(a.x) + fabsf(a.y) + fabsf(a.z) + fabsf(a.w);
        s1 += fabsf(b.x) + fabsf(b.y) + fabsf(b.z) + fabsf(b.w);
        s2 += fabsf(c.x) + fabsf(c.y) + fabsf(c.z) + fabsf(c.w);
        s3 += fabsf(d.x) + fabsf(d.y) + fabsf(d.z) + fabsf(d.w);
    }
    for (; i < N4; i += stride) {
        float4 a = w4[i];
        s0 += fabsf(a.x) + fabsf(a.y) + fabsf(a.z) + fabsf(a.w);
    }
    sm[threadIdx.x] = (s0 + s1) + (s2 + s3);
    __syncthreads();
    for (int o = 128; o > 0; o >>= 1) {
        if (threadIdx.x < o) sm[threadIdx.x] += sm[threadIdx.x + o];
        __syncthreads();
    }
    if (threadIdx.x == 0) g_partials[blockIdx.x] = sm[0];
}

/* ------------------------------------------------------------------ */
/* pass 2: block 0 finalizes (double) ; other blocks split x to fp16   */
/* ------------------------------------------------------------------ */
__global__ void k_fx(const float* __restrict__ x) {
    if (blockIdx.x == 0) {
        __shared__ double sd[256];
        double s = 0.0;
        for (int i = threadIdx.x; i < RBLOCKS; i += 256)
            s += (double)g_partials[i];
        sd[threadIdx.x] = s;
        __syncthreads();
        for (int o = 128; o > 0; o >>= 1) {
            if (threadIdx.x < o) sd[threadIdx.x] += sd[threadIdx.x + o];
            __syncthreads();
        }
        if (threadIdx.x == 0) {
            double mean = sd[0] / (double)NELEM;
            float am = fmaxf((float)mean, 1e-5f);
            g_scale = am;
            g_thr = 0.7f * am;
        }
    } else {
        int i = (blockIdx.x - 1) * 256 + threadIdx.x;
        if (i < TOK * IN_F) g_xh[i] = __float2half(x[i]);
    }
}

/* ------------------------------------------------------------------ */
/* pass 3: partial dequant-GEMM. grid = 86*16 = 1376 CTAs x 256 thr,   */
/* 3 CTAs/SM. Item = (M-tile 128 outs, K-chunk 256). 8 warps x 16 outs.*/
/* Single fp16 x stream; ternarize on the fma pipe (FSETP/FSEL/F2FP).  */
/* W: per-warp cp.async ring, 3 bufs x k32, 8 stages, wait_group 2;    */
/* one commit per stage (empty in tail) keeps group count exact.       */
/* Partials stored as fp16 (half the epilogue/combine traffic).        */
/* ------------------------------------------------------------------ */
__global__ __launch_bounds__(256, 3) void k_gemm(const float* __restrict__ w) {
    extern __shared__ __align__(16) char smem[];
    uint32_t sbase = smem_u32(smem);

    const int tid = threadIdx.x;
    const int lane = tid & 31;
    const int wid = tid >> 5;

    const int tile = (MTILES - 1) - (blockIdx.x >> 4);   /* reverse order */
    const int ks = blockIdx.x & 15;
    const int k0 = ks * KSP;

    const int o_base = tile * 128 + wid * 16;

    /* ---- per-warp W ring setup ---- */
    const uint32_t wring = sbase + XSMEM + wid * WRING;
    const int lrow = lane >> 3;                 /* 0..3: row within op  */
    const int lcol = lane & 7;                  /* 16B column           */
    const float* gw = w + (size_t)o_base * IN_F + k0;
    const float* gsrc = gw + (size_t)lrow * IN_F + lcol * 4;
    const uint32_t sdst = wring + lrow * WROW + lcol * 16;

    /* issue stage s into buffer b (k columns s*32..s*32+31) */
#define W_ISSUE(s, b)                                                        \
    do {                                                                     \
        _Pragma("unroll")                                                    \
        for (int op = 0; op < 4; op++)                                       \
            cp16(sdst + (b) * WBUF + op * 4 * WROW,                          \
                 gsrc + (size_t)op * 4 * IN_F + (s) * 32);                   \
        asm volatile("cp.async.commit_group;" ::: "memory");                 \
    } while (0)

    /* prologue: fill all 3 buffers (overlaps with x staging below) */
    W_ISSUE(0, 0); W_ISSUE(1, 1); W_ISSUE(2, 2);

    /* ---- stage x chunk (fp16) into padded SMEM ---- */
    {
        const uint4* srcx = reinterpret_cast<const uint4*>(g_xh);
#pragma unroll
        for (int e = 0; e < (TOK * KSP / 8) / 256; e++) {
            int g = e * 256 + tid;
            int tok = g >> 5;                   /* KSP/8 = 32 groups/row */
            int kg = g & 31;
            uint4 hv = srcx[(tok * IN_F + k0) / 8 + kg];
            uint32_t dst = sbase + (uint32_t)(tok * PK + kg * 8) * 2;
            asm volatile("st.shared.v4.b32 [%0], {%1,%2,%3,%4};"
                         :: "r"(dst), "r"(hv.x), "r"(hv.y), "r"(hv.z), "r"(hv.w)
                         : "memory");
        }
    }

    const float thr = g_thr;
    const int kq = 2 * (lane & 3);
    const int nrow = lane >> 2;

    /* W consumption address inside a buffer */
    const uint32_t wrd = wring + nrow * WROW;

    /* ldmatrix A addresses */
    const int mrow = ((lane >> 3) & 1) * 8 + (lane & 7);
    const int mcol = (lane >> 4) * 8;
    const uint32_t am0 = sbase + (uint32_t)((0 * 16 + mrow) * PK + mcol) * 2;
    const uint32_t am1 = sbase + (uint32_t)((1 * 16 + mrow) * PK + mcol) * 2;

    float acc[2][2][4];
#pragma unroll
    for (int t = 0; t < 2; t++)
#pragma unroll
        for (int n = 0; n < 2; n++)
#pragma unroll
            for (int r = 0; r < 4; r++) acc[t][n][r] = 0.f;

    __syncthreads();   /* x tiles visible to all warps */

    /* ---- mainloop: 8 stages of k32, per-warp async pipeline ---- */
#pragma unroll 1
    for (int s = 0; s < NSTAGE; s++) {
        asm volatile("cp.async.wait_group 2;" ::: "memory");
        __syncwarp();

        const int buf = s % WNBUF;
        const uint32_t wb = wrd + buf * WBUF;
#pragma unroll
        for (int j = 0; j < 2; j++) {
            const int kk = s * 32 + j * 16;
            const uint32_t o4 = (uint32_t)(j * 16 + kq) * 4;

            float2 u00 = lds_v2(wb + o4);
            float2 u01 = lds_v2(wb + o4 + 32);
            float2 u10 = lds_v2(wb + 8 * WROW + o4);
            float2 u11 = lds_v2(wb + 8 * WROW + o4 + 32);

            uint32_t a0[4], a1[4];
            ldsm_x4(a0, am0 + kk * 2);
            ldsm_x4(a1, am1 + kk * 2);

            uint32_t b00 = tpackf(u00.x, u00.y, thr);
            uint32_t b01 = tpackf(u01.x, u01.y, thr);
            uint32_t b10 = tpackf(u10.x, u10.y, thr);
            uint32_t b11 = tpackf(u11.x, u11.y, thr);

            mma_f16(acc[0][0], a0, b00, b01);
            mma_f16(acc[1][0], a1, b00, b01);
            mma_f16(acc[0][1], a0, b10, b11);
            mma_f16(acc[1][1], a1, b10, b11);
        }

        __syncwarp();
        if (s + WNBUF < NSTAGE) {
            W_ISSUE(s + WNBUF, buf);
        } else {
            /* tail: empty group keeps the wait_group 2 arithmetic exact */
            asm volatile("cp.async.commit_group;" ::: "memory");
        }
    }

    /* ---- epilogue: write fp16 partials (unscaled) ---- */
    __half* dst = g_part[ks];
#pragma unroll
    for (int tt = 0; tt < 2; tt++) {
#pragma unroll
        for (int nt = 0; nt < 2; nt++) {
            int tok = tt * 16 + (lane >> 2);
            int o = o_base + nt * 8 + kq;     /* even -> 4B aligned */
            __half2 lo = __floats2half2_rn(acc[tt][nt][0], acc[tt][nt][1]);
            __half2 hi = __floats2half2_rn(acc[tt][nt][2], acc[tt][nt][3]);
            *reinterpret_cast<__half2*>(dst + (size_t)tok * OUT_F + o) = lo;
            *reinterpret_cast<__half2*>(dst + (size_t)(tok + 8) * OUT_F + o) = hi;
        }
    }
#undef W_ISSUE
}

/* ------------------------------------------------------------------ */
/* pass 4: combine 16 fp16 partials, apply scale. launch_bounds keeps  */
/* the register budget high enough to batch all 16 loads (full MLP).   */
/* ------------------------------------------------------------------ */
__global__ __launch_bounds__(256, 2) void k_combine(float* __restrict__ out) {
    const float scale = g_scale;
    int i = blockIdx.x * 256 + threadIdx.x;      /* uint2 idx: 4 outputs */
    if (i < TOK * OUT_F / 4) {
        float sx = 0.f, sy = 0.f, sz = 0.f, sw = 0.f;
#pragma unroll
        for (int p = 0; p < SPLITS; p++) {
            uint2 v = reinterpret_cast<const uint2*>(g_part[p])[i];
            float2 f0 = __half22float2(*reinterpret_cast<__half2*>(&v.x));
            float2 f1 = __half22float2(*reinterpret_cast<__half2*>(&v.y));
            sx += f0.x; sy += f0.y; sz += f1.x; sw += f1.y;
        }
        float4 r;
        r.x = sx * scale; r.y = sy * scale; r.z = sz * scale; r.w = sw * scale;
        reinterpret_cast<float4*>(out)[i] = r;
    }
}

/* ------------------------------------------------------------------ */
extern "C" void kernel_launch(void* const* d_in, const int* in_sizes, int n_in,
                              void* d_out, int out_size) {
    const float* x = (const float*)d_in[0];
    const float* w = (const float*)d_in[1];
    float* out = (float*)d_out;
    (void)in_sizes; (void)n_in; (void)out_size;

    cudaFuncSetAttribute(k_gemm, cudaFuncAttributeMaxDynamicSharedMemorySize,
                         GEMM_SMEM);

    k_reduce<<<RBLOCKS, 256>>>(w);
    k_fx<<<1 + (TOK * IN_F + 255) / 256, 256>>>(x);
    k_gemm<<<MTILES * SPLITS, 256, GEMM_SMEM>>>(w);
    k_combine<<<(TOK * OUT_F / 4 + 255) / 256, 256>>>(out);
}